// round 8
// baseline (speedup 1.0000x reference)
#include <cuda_runtime.h>
#include <stdint.h>

// ---------------------------------------------------------------------------
// Winograd F(2,3) valid conv, tf32 mma.sync with FUSED inverse transform:
//   1) filt_xform : U[p][c][k] = G g G^T        (tf32-rounded, k-contig)
//   2) in_xform   : V[p][c][t] = B^T d B        (tf32-rounded, t-contig)
//   3) wino_fused : per CTA (kb,tb): loop p=0..15, GEMM M_p tile (64k x 32t,
//      c=128) on tensor cores, fold At M_p A into 4 output accumulators,
//      write out + bias directly.  No M tensor (saves 1.01 GB DRAM traffic
//      and the separate out_xform kernel).
//   cp.async 4-stage pipeline, one __syncthreads per 8-c chunk.
// ---------------------------------------------------------------------------

#define Bn 32
#define Cc 128
#define Hh 64
#define Ww 64
#define Kk 256
#define NT (Bn * 31 * 31)     /* 30752 */
#define NTP 30848             /* 964 * 32 */
#define OH 62
#define OW 62
#define NCH 256               /* 16 p * 16 c-chunks */

__device__ float g_U[16 * Cc * Kk];      //   2 MB  [p][c][k]
__device__ float g_V[16 * Cc * NTP];     // 253 MB  [p][c][t]  (pad region stays 0)

__device__ __forceinline__ float to_tf32(float x) {
    uint32_t r;
    asm("cvt.rna.tf32.f32 %0, %1;" : "=r"(r) : "f"(x));
    return __uint_as_float(r);
}
__device__ __forceinline__ uint32_t smem_u32(const void* p) {
    uint32_t a;
    asm("{ .reg .u64 t; cvta.to.shared.u64 t, %1; cvt.u32.u64 %0, t; }" : "=r"(a) : "l"(p));
    return a;
}
__device__ __forceinline__ void mma_tf32(float* d, const uint32_t* a, const uint32_t* b) {
    asm volatile(
        "mma.sync.aligned.m16n8k8.row.col.f32.tf32.tf32.f32 "
        "{%0,%1,%2,%3}, {%4,%5,%6,%7}, {%8,%9}, {%0,%1,%2,%3};"
        : "+f"(d[0]), "+f"(d[1]), "+f"(d[2]), "+f"(d[3])
        : "r"(a[0]), "r"(a[1]), "r"(a[2]), "r"(a[3]), "r"(b[0]), "r"(b[1]));
}
__device__ __forceinline__ void cp16(uint32_t dst, const void* src) {
    asm volatile("cp.async.cg.shared.global [%0], [%1], 16;" :: "r"(dst), "l"(src));
}

// ---------------------------------------------------------------------------
// 1) Filter transform -> U[p][c][k]
// ---------------------------------------------------------------------------
__global__ void filt_xform(const float* __restrict__ w)
{
    int idx = blockIdx.x * blockDim.x + threadIdx.x;
    int k = idx >> 7;
    int c = idx & 127;
    const float* g = w + (size_t)(k * Cc + c) * 9;

    float w00 = g[0], w01 = g[1], w02 = g[2];
    float w10 = g[3], w11 = g[4], w12 = g[5];
    float w20 = g[6], w21 = g[7], w22 = g[8];

    float t[4][3];
    t[0][0] = w00;                      t[0][1] = w01;                      t[0][2] = w02;
    t[1][0] = 0.5f * (w00 + w10 + w20); t[1][1] = 0.5f * (w01 + w11 + w21); t[1][2] = 0.5f * (w02 + w12 + w22);
    t[2][0] = 0.5f * (w00 - w10 + w20); t[2][1] = 0.5f * (w01 - w11 + w21); t[2][2] = 0.5f * (w02 - w12 + w22);
    t[3][0] = w20;                      t[3][1] = w21;                      t[3][2] = w22;

    #pragma unroll
    for (int a = 0; a < 4; a++) {
        float u0 = t[a][0];
        float u1 = 0.5f * (t[a][0] + t[a][1] + t[a][2]);
        float u2 = 0.5f * (t[a][0] - t[a][1] + t[a][2]);
        float u3 = t[a][2];
        g_U[((size_t)(a * 4 + 0) * Cc + c) * Kk + k] = to_tf32(u0);
        g_U[((size_t)(a * 4 + 1) * Cc + c) * Kk + k] = to_tf32(u1);
        g_U[((size_t)(a * 4 + 2) * Cc + c) * Kk + k] = to_tf32(u2);
        g_U[((size_t)(a * 4 + 3) * Cc + c) * Kk + k] = to_tf32(u3);
    }
}

// ---------------------------------------------------------------------------
// 2) Input transform -> V[p][c][t]
// ---------------------------------------------------------------------------
__global__ void in_xform(const float* __restrict__ x)
{
    unsigned idx = blockIdx.x * blockDim.x + threadIdx.x;   // < Cc*NT exact
    unsigned c = idx / NT;
    unsigned t = idx - c * NT;
    unsigned b  = t / 961u;
    unsigned r  = t - b * 961u;
    unsigned pp = r / 31u;
    unsigned qq = r - pp * 31u;

    const float* xp = x + (((size_t)(b * Cc + c) * Hh + 2u * pp) * Ww + 2u * qq);

    float d[4][4];
    #pragma unroll
    for (int i = 0; i < 4; i++)
        #pragma unroll
        for (int j = 0; j < 4; j++)
            d[i][j] = xp[i * Ww + j];

    float tm[4][4];
    #pragma unroll
    for (int j = 0; j < 4; j++) {
        tm[0][j] = d[0][j] - d[2][j];
        tm[1][j] = d[1][j] + d[2][j];
        tm[2][j] = d[2][j] - d[1][j];
        tm[3][j] = d[1][j] - d[3][j];
    }

    #pragma unroll
    for (int a = 0; a < 4; a++) {
        float v0 = tm[a][0] - tm[a][2];
        float v1 = tm[a][1] + tm[a][2];
        float v2 = tm[a][2] - tm[a][1];
        float v3 = tm[a][1] - tm[a][3];
        g_V[((size_t)(a * 4 + 0) * Cc + c) * NTP + t] = to_tf32(v0);
        g_V[((size_t)(a * 4 + 1) * Cc + c) * NTP + t] = to_tf32(v1);
        g_V[((size_t)(a * 4 + 2) * Cc + c) * NTP + t] = to_tf32(v2);
        g_V[((size_t)(a * 4 + 3) * Cc + c) * NTP + t] = to_tf32(v3);
    }
}

// ---------------------------------------------------------------------------
// 3) Fused GEMM + inverse transform.
//    Chunk stream it=0..255:  p=it>>4, cc=it&15; contiguous c index = it*8.
//    Stage: U 8c x 64k (pitch 72 fl) + V 8c x 32t (pitch 40 fl) = 3584 B, x4.
// ---------------------------------------------------------------------------
#define STAGE_B 3584            /* (8*72 + 8*40) * 4 */
#define V_OFF   2304            /* 8*72*4 */

__global__ void __launch_bounds__(256, 2) wino_fused(const float* __restrict__ bias,
                                                     float* __restrict__ out)
{
    __shared__ alignas(16) char smem[4 * STAGE_B];
    const uint32_t sb = smem_u32(smem);

    const int kb = blockIdx.x;          // 0..3  (fastest -> kb peers share V in L2)
    const int tb = blockIdx.y;          // 0..963
    const int tid  = threadIdx.x;
    const int wid  = tid >> 5, lane = tid & 31;
    const int g    = lane >> 2, tig = lane & 3;
    const int wk   = (wid & 3) * 16;    // warp k origin (CTA k-tile 64)
    const int wt   = (wid >> 2) * 16;   // warp t origin (CTA t-tile 32)

    // ---- per-thread cp.async role -------------------------------------
    const bool loader = tid < 192;
    const float* gbase = nullptr;
    size_t gstep = 0;
    uint32_t soff = 0;
    if (tid < 128) {                    // U: 128 threads, 8c x 16 float4
        int crow = tid >> 4, kq = (tid & 15) * 4;
        gbase = g_U + (size_t)crow * Kk + kb * 64 + kq;
        gstep = (size_t)8 * Kk;
        soff  = (uint32_t)(crow * 288 + kq * 4);
    } else if (tid < 192) {             // V: 64 threads, 8c x 8 float4
        int j = tid - 128;
        int crow = j >> 3, tq = (j & 7) * 4;
        gbase = g_V + (size_t)crow * NTP + (size_t)tb * 32 + tq;
        gstep = (size_t)8 * NTP;
        soff  = (uint32_t)(V_OFF + crow * 160 + tq * 4);
    }

    // ---- accumulators --------------------------------------------------
    float acc[2][4];                    // M_p fragment (per p, reset each p)
    float y[2][4][4];                   // output accumulators {y00,y01,y10,y11}
    #pragma unroll
    for (int nj = 0; nj < 2; nj++) {
        #pragma unroll
        for (int q = 0; q < 4; q++) {
            acc[nj][q] = 0.0f;
            #pragma unroll
            for (int e = 0; e < 4; e++) y[nj][q][e] = 0.0f;
        }
    }

    // ---- prefetch stages 0..2 ------------------------------------------
    #pragma unroll
    for (int s = 0; s < 3; s++) {
        if (loader) cp16(sb + (uint32_t)(s & 3) * STAGE_B + soff, gbase + (size_t)s * gstep);
        asm volatile("cp.async.commit_group;" ::: "memory");
    }

    // ---- mainloop -------------------------------------------------------
    #pragma unroll 1
    for (int it = 0; it < NCH; it++) {
        asm volatile("cp.async.wait_group %0;" :: "n"(2) : "memory");
        __syncthreads();

        const float* S  = (const float*)(smem + (it & 3) * STAGE_B);
        const float* Sv = (const float*)(smem + (it & 3) * STAGE_B + V_OFF);

        uint32_t a[4];
        a[0] = __float_as_uint(S[tig * 72 + wk + g]);
        a[1] = __float_as_uint(S[tig * 72 + wk + g + 8]);
        a[2] = __float_as_uint(S[(tig + 4) * 72 + wk + g]);
        a[3] = __float_as_uint(S[(tig + 4) * 72 + wk + g + 8]);
        #pragma unroll
        for (int nj = 0; nj < 2; nj++) {
            uint32_t b[2];
            b[0] = __float_as_uint(Sv[tig * 40 + wt + 8 * nj + g]);
            b[1] = __float_as_uint(Sv[(tig + 4) * 40 + wt + 8 * nj + g]);
            mma_tf32(acc[nj], a, b);
        }

        if ((it & 15) == 15) {          // end of point p: fold At M_p A into y
            int p = it >> 4;
            int i = p >> 2, j = p & 3;
            float A0i = (i == 3) ? 0.f : 1.f;
            float A1i = (i == 0) ? 0.f : ((i == 1) ? 1.f : -1.f);
            float A0j = (j == 3) ? 0.f : 1.f;
            float A1j = (j == 0) ? 0.f : ((j == 1) ? 1.f : -1.f);
            float w00 = A0i * A0j, w01 = A0i * A1j;
            float w10 = A1i * A0j, w11 = A1i * A1j;
            #pragma unroll
            for (int nj = 0; nj < 2; nj++)
                #pragma unroll
                for (int q = 0; q < 4; q++) {
                    float m = acc[nj][q];
                    y[nj][q][0] += w00 * m;
                    y[nj][q][1] += w01 * m;
                    y[nj][q][2] += w10 * m;
                    y[nj][q][3] += w11 * m;
                    acc[nj][q] = 0.0f;
                }
        }

        int nx = it + 3;
        if (nx < NCH) {
            if (loader) cp16(sb + (uint32_t)(nx & 3) * STAGE_B + soff, gbase + (size_t)nx * gstep);
        }
        asm volatile("cp.async.commit_group;" ::: "memory");
    }

    // ---- epilogue: write 2x2 outputs + bias ------------------------------
    float bv0 = __ldg(bias + kb * 64 + wk + g);
    float bv1 = __ldg(bias + kb * 64 + wk + g + 8);

    #pragma unroll
    for (int nj = 0; nj < 2; nj++) {
        #pragma unroll
        for (int s = 0; s < 2; s++) {
            int t = tb * 32 + wt + 8 * nj + 2 * tig + s;
            if (t < NT) {
                int b_ = t / 961, r = t - b_ * 961;
                int pp = r / 31, qq = r - pp * 31;
                float* op = out + (((size_t)b_ * Kk + kb * 64 + wk + g) * OH + 2 * pp) * OW + 2 * qq;
                *(float2*)op        = make_float2(y[nj][s][0] + bv0, y[nj][s][1] + bv0);
                *(float2*)(op + OW) = make_float2(y[nj][s][2] + bv0, y[nj][s][3] + bv0);
                float* op2 = op + (size_t)8 * OH * OW;
                *(float2*)op2        = make_float2(y[nj][2 + s][0] + bv1, y[nj][2 + s][1] + bv1);
                *(float2*)(op2 + OW) = make_float2(y[nj][2 + s][2] + bv1, y[nj][2 + s][3] + bv1);
            }
        }
    }
}

// ---------------------------------------------------------------------------
extern "C" void kernel_launch(void* const* d_in, const int* in_sizes, int n_in,
                              void* d_out, int out_size)
{
    const float* x    = (const float*)d_in[0];
    const float* w    = (const float*)d_in[1];
    const float* bias = (const float*)d_in[2];
    float* out        = (float*)d_out;

    filt_xform<<<(Kk * Cc) / 256, 256>>>(w);
    in_xform<<<(Cc * NT) / 256, 256>>>(x);
    dim3 gf(4, NTP / 32);                     // (kb, tb) = (4, 964)
    wino_fused<<<gf, 256>>>(bias, out);
}

// round 9
// speedup vs baseline: 1.9353x; 1.9353x over previous
#include <cuda_runtime.h>
#include <cuda_fp16.h>
#include <stdint.h>

// ---------------------------------------------------------------------------
// Winograd F(2,3) valid conv, fp16 mma.sync (m16n8k16, fp32 accum):
//   1) filt_xform : U[p][c][k] = G g G^T   (fp16, k-contig)
//   2) in_xform   : V[p][c][t] = B^T d B   (fp16, t-contig)
//   3) wino_gemm  : M[p][k][t] = sum_c U*V (fp16 HMMA, fp32 acc, ldmatrix)
//   4) out_xform  : Y = A^T M A + bias
// fp16 mantissa (10 bits) == tf32 mantissa -> same rel_err as round 7 (4.9e-4),
// but 2x tensor throughput and half the operand DRAM traffic.
// ---------------------------------------------------------------------------

#define Bn 32
#define Cc 128
#define Hh 64
#define Ww 64
#define Kk 256
#define NT (Bn * 31 * 31)     /* 30752 */
#define NTP 30848             /* 241 * 128 */
#define OH 62
#define OW 62

__device__ __half g_U16[16 * Cc * Kk];    //   1 MB  [p][c][k]
__device__ __half g_V16[16 * Cc * NTP];   // 126 MB  [p][c][t]
__device__ float  g_M[16 * Kk * NTP];     // 505 MB  [p][k][t]

__device__ __forceinline__ uint32_t smem_u32(const void* p) {
    uint32_t a;
    asm("{ .reg .u64 t; cvta.to.shared.u64 t, %1; cvt.u32.u64 %0, t; }" : "=r"(a) : "l"(p));
    return a;
}
__device__ __forceinline__ void cp16(uint32_t dst, const void* src) {
    asm volatile("cp.async.cg.shared.global [%0], [%1], 16;" :: "r"(dst), "l"(src));
}
__device__ __forceinline__ void ldmx4(uint32_t* r, uint32_t addr) {
    asm volatile("ldmatrix.sync.aligned.m8n8.x4.trans.shared.b16 {%0,%1,%2,%3}, [%4];"
                 : "=r"(r[0]), "=r"(r[1]), "=r"(r[2]), "=r"(r[3]) : "r"(addr));
}
__device__ __forceinline__ void mma_f16(float* d, const uint32_t* a, const uint32_t* b) {
    asm volatile(
        "mma.sync.aligned.m16n8k16.row.col.f32.f16.f16.f32 "
        "{%0,%1,%2,%3}, {%4,%5,%6,%7}, {%8,%9}, {%0,%1,%2,%3};"
        : "+f"(d[0]), "+f"(d[1]), "+f"(d[2]), "+f"(d[3])
        : "r"(a[0]), "r"(a[1]), "r"(a[2]), "r"(a[3]), "r"(b[0]), "r"(b[1]));
}

// ---------------------------------------------------------------------------
// 1) Filter transform -> U[p][c][k] fp16
// ---------------------------------------------------------------------------
__global__ void filt_xform(const float* __restrict__ w)
{
    int idx = blockIdx.x * blockDim.x + threadIdx.x;   // 32768
    int k = idx >> 7;
    int c = idx & 127;
    const float* g = w + (size_t)(k * Cc + c) * 9;

    float w00 = g[0], w01 = g[1], w02 = g[2];
    float w10 = g[3], w11 = g[4], w12 = g[5];
    float w20 = g[6], w21 = g[7], w22 = g[8];

    float t[4][3];
    t[0][0] = w00;                      t[0][1] = w01;                      t[0][2] = w02;
    t[1][0] = 0.5f * (w00 + w10 + w20); t[1][1] = 0.5f * (w01 + w11 + w21); t[1][2] = 0.5f * (w02 + w12 + w22);
    t[2][0] = 0.5f * (w00 - w10 + w20); t[2][1] = 0.5f * (w01 - w11 + w21); t[2][2] = 0.5f * (w02 - w12 + w22);
    t[3][0] = w20;                      t[3][1] = w21;                      t[3][2] = w22;

    #pragma unroll
    for (int a = 0; a < 4; a++) {
        float u0 = t[a][0];
        float u1 = 0.5f * (t[a][0] + t[a][1] + t[a][2]);
        float u2 = 0.5f * (t[a][0] - t[a][1] + t[a][2]);
        float u3 = t[a][2];
        g_U16[((size_t)(a * 4 + 0) * Cc + c) * Kk + k] = __float2half_rn(u0);
        g_U16[((size_t)(a * 4 + 1) * Cc + c) * Kk + k] = __float2half_rn(u1);
        g_U16[((size_t)(a * 4 + 2) * Cc + c) * Kk + k] = __float2half_rn(u2);
        g_U16[((size_t)(a * 4 + 3) * Cc + c) * Kk + k] = __float2half_rn(u3);
    }
}

// ---------------------------------------------------------------------------
// 2) Input transform -> V[p][c][t] fp16 (t contiguous)
// ---------------------------------------------------------------------------
__global__ void in_xform(const float* __restrict__ x)
{
    unsigned idx = blockIdx.x * blockDim.x + threadIdx.x;   // < Cc*NT exact
    unsigned c = idx / NT;
    unsigned t = idx - c * NT;
    unsigned b  = t / 961u;
    unsigned r  = t - b * 961u;
    unsigned pp = r / 31u;
    unsigned qq = r - pp * 31u;

    const float* xp = x + (((size_t)(b * Cc + c) * Hh + 2u * pp) * Ww + 2u * qq);

    float d[4][4];
    #pragma unroll
    for (int i = 0; i < 4; i++)
        #pragma unroll
        for (int j = 0; j < 4; j++)
            d[i][j] = xp[i * Ww + j];

    float tm[4][4];
    #pragma unroll
    for (int j = 0; j < 4; j++) {
        tm[0][j] = d[0][j] - d[2][j];
        tm[1][j] = d[1][j] + d[2][j];
        tm[2][j] = d[2][j] - d[1][j];
        tm[3][j] = d[1][j] - d[3][j];
    }

    #pragma unroll
    for (int a = 0; a < 4; a++) {
        float v0 = tm[a][0] - tm[a][2];
        float v1 = tm[a][1] + tm[a][2];
        float v2 = tm[a][2] - tm[a][1];
        float v3 = tm[a][1] - tm[a][3];
        g_V16[((size_t)(a * 4 + 0) * Cc + c) * NTP + t] = __float2half_rn(v0);
        g_V16[((size_t)(a * 4 + 1) * Cc + c) * NTP + t] = __float2half_rn(v1);
        g_V16[((size_t)(a * 4 + 2) * Cc + c) * NTP + t] = __float2half_rn(v2);
        g_V16[((size_t)(a * 4 + 3) * Cc + c) * NTP + t] = __float2half_rn(v3);
    }
}

// ---------------------------------------------------------------------------
// 3) fp16 tensor GEMM:  M[k][t] = sum_c U[c][k] * V[c][t], per point p.
//    CTA 128k x 128t, 256 thr, warp tile 32k x 64t (mi2 x nj8 = 16 HMMA/chunk).
//    Chunks of 16 c, cp.async 4-deep ring, 1 sync/chunk, ldmatrix.x4.trans.
//    Smem stage: U 16c x 128k + V 16c x 128t halves, pitch 136 halves (272 B).
//    grid = (kb=2 fastest, tb=241, p=16)
// ---------------------------------------------------------------------------
#define PITCH_B 272             /* bytes per smem row (136 halves) */
#define UREG_B  4352            /* 16 rows * 272 */
#define STAGE_B 8704            /* U + V regions */

__global__ void __launch_bounds__(256, 2) wino_gemm()
{
    __shared__ alignas(16) char smem[4 * STAGE_B];
    const uint32_t sb = smem_u32(smem);

    const int kb = blockIdx.x;          // 0..1  (fastest: peers share V in L2)
    const int tb = blockIdx.y;          // 0..240
    const int p  = blockIdx.z;          // 0..15

    const int tid  = threadIdx.x;
    const int wid  = tid >> 5, lane = tid & 31;
    const int g    = lane >> 2, tig = lane & 3;
    const int wk   = (wid & 3) * 32;
    const int wt   = (wid >> 2) * 64;

    // ---- cp.async loader role: all 256 threads, 2 x 16B each per chunk ----
    const __half* gptr;
    size_t gstep;
    uint32_t soff;
    {
        if (tid < 128) {                 // U: 16 c-rows x 128 k halves (256 B)
            int row = tid >> 3, seg = tid & 7;
            gptr  = g_U16 + ((size_t)p * Cc + row) * Kk + kb * 128 + seg * 8;
            gstep = (size_t)16 * Kk;
            soff  = (uint32_t)(row * PITCH_B + seg * 16);
        } else {                         // V: 16 c-rows x 128 t halves
            int j = tid - 128;
            int row = j >> 3, seg = j & 7;
            gptr  = g_V16 + ((size_t)p * Cc + row) * NTP + (size_t)tb * 128 + seg * 8;
            gstep = (size_t)16 * NTP;
            soff  = (uint32_t)(UREG_B + row * PITCH_B + seg * 16);
        }
    }
    // second 16B segment sits 64 halves (128 B) later in both gmem and smem.

    // ---- ldmatrix lane offsets -----------------------------------------
    // A (row.col M=k-out, K=c) from Us[c][k]: x4.trans
    const uint32_t aoff0 = (uint32_t)(((lane & 7) + ((lane >> 4) & 1) * 8) * PITCH_B
                                      + (wk + ((lane >> 3) & 1) * 8) * 2);
    // B from Vs[c][t]: x4.trans (covers two nj n0, n0+8)
    const uint32_t boff0 = (uint32_t)(UREG_B
                                      + ((lane & 7) + ((lane >> 3) & 1) * 8) * PITCH_B
                                      + (wt + ((lane >> 4) & 1) * 8) * 2);

    float acc[2][8][4];
    #pragma unroll
    for (int mi = 0; mi < 2; mi++)
        #pragma unroll
        for (int nj = 0; nj < 8; nj++)
            #pragma unroll
            for (int q = 0; q < 4; q++)
                acc[mi][nj][q] = 0.0f;

    // ---- prefetch stages 0..2 ------------------------------------------
    #pragma unroll
    for (int s = 0; s < 3; s++) {
        uint32_t d = sb + (uint32_t)s * STAGE_B + soff;
        cp16(d,       gptr + (size_t)s * gstep);
        cp16(d + 128, gptr + (size_t)s * gstep + 64);
        asm volatile("cp.async.commit_group;" ::: "memory");
    }

    // ---- mainloop: 8 chunks of 16 c --------------------------------------
    #pragma unroll 1
    for (int it = 0; it < 8; it++) {
        asm volatile("cp.async.wait_group %0;" :: "n"(2) : "memory");
        __syncthreads();

        const uint32_t buf = sb + (uint32_t)(it & 3) * STAGE_B;

        uint32_t a[2][4];
        ldmx4(a[0], buf + aoff0);
        ldmx4(a[1], buf + aoff0 + 32);          // mi=1: m0+16 halves
        uint32_t bb[4][4];
        #pragma unroll
        for (int njp = 0; njp < 4; njp++)
            ldmx4(bb[njp], buf + boff0 + njp * 32);   // n0 + 16*njp halves

        #pragma unroll
        for (int mi = 0; mi < 2; mi++)
            #pragma unroll
            for (int njp = 0; njp < 4; njp++) {
                mma_f16(acc[mi][njp * 2 + 0], a[mi], &bb[njp][0]);
                mma_f16(acc[mi][njp * 2 + 1], a[mi], &bb[njp][2]);
            }

        int nx = it + 3;
        if (nx < 8) {
            uint32_t d = sb + (uint32_t)(nx & 3) * STAGE_B + soff;
            cp16(d,       gptr + (size_t)nx * gstep);
            cp16(d + 128, gptr + (size_t)nx * gstep + 64);
        }
        asm volatile("cp.async.commit_group;" ::: "memory");
    }

    // ---- epilogue: fp32 M stores ----------------------------------------
    float* Mp = g_M + ((size_t)p * Kk + kb * 128 + wk) * NTP + (size_t)tb * 128 + wt;
    #pragma unroll
    for (int mi = 0; mi < 2; mi++) {
        #pragma unroll
        for (int nj = 0; nj < 8; nj++) {
            int t_off = nj * 8 + 2 * tig;
            float* r0 = Mp + (size_t)(mi * 16 + g) * NTP + t_off;
            *(float2*)r0                     = make_float2(acc[mi][nj][0], acc[mi][nj][1]);
            *(float2*)(r0 + (size_t)8 * NTP) = make_float2(acc[mi][nj][2], acc[mi][nj][3]);
        }
    }
}

// ---------------------------------------------------------------------------
// 4) Inverse transform + bias (DRAM roofline)
// ---------------------------------------------------------------------------
__global__ void out_xform(const float* __restrict__ bias, float* __restrict__ out)
{
    unsigned idx = blockIdx.x * blockDim.x + threadIdx.x;   // < Kk*NT exact
    unsigned k = idx / NT;
    unsigned t = idx - k * NT;
    unsigned b  = t / 961u;
    unsigned r  = t - b * 961u;
    unsigned pp = r / 31u;
    unsigned qq = r - pp * 31u;

    float m[16];
    #pragma unroll
    for (int p = 0; p < 16; p++)
        m[p] = g_M[((size_t)p * Kk + k) * NTP + t];

    float s0[4], s1[4];
    #pragma unroll
    for (int j = 0; j < 4; j++) {
        s0[j] = m[j] + m[4 + j] + m[8 + j];
        s1[j] = m[4 + j] - m[8 + j] - m[12 + j];
    }
    float bv = __ldg(bias + k);
    float y00 = s0[0] + s0[1] + s0[2] + bv;
    float y01 = s0[1] - s0[2] - s0[3] + bv;
    float y10 = s1[0] + s1[1] + s1[2] + bv;
    float y11 = s1[1] - s1[2] - s1[3] + bv;

    float* op = out + (((size_t)b * Kk + k) * OH + 2u * pp) * OW + 2u * qq;
    *(float2*)op        = make_float2(y00, y01);
    *(float2*)(op + OW) = make_float2(y10, y11);
}

// ---------------------------------------------------------------------------
extern "C" void kernel_launch(void* const* d_in, const int* in_sizes, int n_in,
                              void* d_out, int out_size)
{
    const float* x    = (const float*)d_in[0];
    const float* w    = (const float*)d_in[1];
    const float* bias = (const float*)d_in[2];
    float* out        = (float*)d_out;

    filt_xform<<<(Kk * Cc) / 256, 256>>>(w);
    in_xform<<<(Cc * NT) / 256, 256>>>(x);
    dim3 g3(2, 241, 16);                       // (kb, tb, p), kb fastest
    wino_gemm<<<g3, 256>>>();
    out_xform<<<(Kk * NT) / 256, 256>>>(bias, out);
}

// round 10
// speedup vs baseline: 2.0871x; 1.0784x over previous
#include <cuda_runtime.h>
#include <cuda_fp16.h>
#include <stdint.h>

// ---------------------------------------------------------------------------
// Winograd F(2,3) valid conv, fp16 mma.sync (m16n8k16, fp32 accum):
//   1) filt_xform : U[p][c][k] = G g G^T   (fp16, k-contig)
//   2) in_xform   : V[p][c][t] = B^T d B   (fp16, t-contig)
//   3) wino_gemm  : M[p][k][t] = sum_c U*V (fp16 HMMA, fp32 acc) -> M in FP16
//   4) out_xform  : Y = A^T M A + bias
// Round-10 change vs round 9: M stored fp16 (505 -> 252 MB), halving the
// gemm store traffic and the out_xform read traffic.
// ---------------------------------------------------------------------------

#define Bn 32
#define Cc 128
#define Hh 64
#define Ww 64
#define Kk 256
#define NT (Bn * 31 * 31)     /* 30752 */
#define NTP 30848             /* 241 * 128 */
#define OH 62
#define OW 62

__device__ __half g_U16[16 * Cc * Kk];    //   1 MB  [p][c][k]
__device__ __half g_V16[16 * Cc * NTP];   // 126 MB  [p][c][t]
__device__ __half g_M16[16 * Kk * NTP];   // 252 MB  [p][k][t]

__device__ __forceinline__ uint32_t smem_u32(const void* p) {
    uint32_t a;
    asm("{ .reg .u64 t; cvta.to.shared.u64 t, %1; cvt.u32.u64 %0, t; }" : "=r"(a) : "l"(p));
    return a;
}
__device__ __forceinline__ void cp16(uint32_t dst, const void* src) {
    asm volatile("cp.async.cg.shared.global [%0], [%1], 16;" :: "r"(dst), "l"(src));
}
__device__ __forceinline__ void ldmx4(uint32_t* r, uint32_t addr) {
    asm volatile("ldmatrix.sync.aligned.m8n8.x4.trans.shared.b16 {%0,%1,%2,%3}, [%4];"
                 : "=r"(r[0]), "=r"(r[1]), "=r"(r[2]), "=r"(r[3]) : "r"(addr));
}
__device__ __forceinline__ void mma_f16(float* d, const uint32_t* a, const uint32_t* b) {
    asm volatile(
        "mma.sync.aligned.m16n8k16.row.col.f32.f16.f16.f32 "
        "{%0,%1,%2,%3}, {%4,%5,%6,%7}, {%8,%9}, {%0,%1,%2,%3};"
        : "+f"(d[0]), "+f"(d[1]), "+f"(d[2]), "+f"(d[3])
        : "r"(a[0]), "r"(a[1]), "r"(a[2]), "r"(a[3]), "r"(b[0]), "r"(b[1]));
}

// ---------------------------------------------------------------------------
// 1) Filter transform -> U[p][c][k] fp16
// ---------------------------------------------------------------------------
__global__ void filt_xform(const float* __restrict__ w)
{
    int idx = blockIdx.x * blockDim.x + threadIdx.x;   // 32768
    int k = idx >> 7;
    int c = idx & 127;
    const float* g = w + (size_t)(k * Cc + c) * 9;

    float w00 = g[0], w01 = g[1], w02 = g[2];
    float w10 = g[3], w11 = g[4], w12 = g[5];
    float w20 = g[6], w21 = g[7], w22 = g[8];

    float t[4][3];
    t[0][0] = w00;                      t[0][1] = w01;                      t[0][2] = w02;
    t[1][0] = 0.5f * (w00 + w10 + w20); t[1][1] = 0.5f * (w01 + w11 + w21); t[1][2] = 0.5f * (w02 + w12 + w22);
    t[2][0] = 0.5f * (w00 - w10 + w20); t[2][1] = 0.5f * (w01 - w11 + w21); t[2][2] = 0.5f * (w02 - w12 + w22);
    t[3][0] = w20;                      t[3][1] = w21;                      t[3][2] = w22;

    #pragma unroll
    for (int a = 0; a < 4; a++) {
        float u0 = t[a][0];
        float u1 = 0.5f * (t[a][0] + t[a][1] + t[a][2]);
        float u2 = 0.5f * (t[a][0] - t[a][1] + t[a][2]);
        float u3 = t[a][2];
        g_U16[((size_t)(a * 4 + 0) * Cc + c) * Kk + k] = __float2half_rn(u0);
        g_U16[((size_t)(a * 4 + 1) * Cc + c) * Kk + k] = __float2half_rn(u1);
        g_U16[((size_t)(a * 4 + 2) * Cc + c) * Kk + k] = __float2half_rn(u2);
        g_U16[((size_t)(a * 4 + 3) * Cc + c) * Kk + k] = __float2half_rn(u3);
    }
}

// ---------------------------------------------------------------------------
// 2) Input transform -> V[p][c][t] fp16 (t contiguous)
// ---------------------------------------------------------------------------
__global__ void in_xform(const float* __restrict__ x)
{
    unsigned idx = blockIdx.x * blockDim.x + threadIdx.x;   // < Cc*NT exact
    unsigned c = idx / NT;
    unsigned t = idx - c * NT;
    unsigned b  = t / 961u;
    unsigned r  = t - b * 961u;
    unsigned pp = r / 31u;
    unsigned qq = r - pp * 31u;

    const float* xp = x + (((size_t)(b * Cc + c) * Hh + 2u * pp) * Ww + 2u * qq);

    float d[4][4];
    #pragma unroll
    for (int i = 0; i < 4; i++)
        #pragma unroll
        for (int j = 0; j < 4; j++)
            d[i][j] = xp[i * Ww + j];

    float tm[4][4];
    #pragma unroll
    for (int j = 0; j < 4; j++) {
        tm[0][j] = d[0][j] - d[2][j];
        tm[1][j] = d[1][j] + d[2][j];
        tm[2][j] = d[2][j] - d[1][j];
        tm[3][j] = d[1][j] - d[3][j];
    }

    #pragma unroll
    for (int a = 0; a < 4; a++) {
        float v0 = tm[a][0] - tm[a][2];
        float v1 = tm[a][1] + tm[a][2];
        float v2 = tm[a][2] - tm[a][1];
        float v3 = tm[a][1] - tm[a][3];
        g_V16[((size_t)(a * 4 + 0) * Cc + c) * NTP + t] = __float2half_rn(v0);
        g_V16[((size_t)(a * 4 + 1) * Cc + c) * NTP + t] = __float2half_rn(v1);
        g_V16[((size_t)(a * 4 + 2) * Cc + c) * NTP + t] = __float2half_rn(v2);
        g_V16[((size_t)(a * 4 + 3) * Cc + c) * NTP + t] = __float2half_rn(v3);
    }
}

// ---------------------------------------------------------------------------
// 3) fp16 tensor GEMM:  M[k][t] = sum_c U[c][k] * V[c][t], per point p.
//    CTA 128k x 128t, 256 thr, warp tile 32k x 64t (16 HMMA/chunk).
//    Chunks of 16 c, cp.async 4-deep ring, 1 sync/chunk, ldmatrix.x4.trans.
//    grid = (kb=2 fastest, tb=241, p=16).  M stored as fp16 (half2 pairs).
// ---------------------------------------------------------------------------
#define PITCH_B 272             /* bytes per smem row (136 halves) */
#define UREG_B  4352            /* 16 rows * 272 */
#define STAGE_B 8704            /* U + V regions */

__global__ void __launch_bounds__(256, 2) wino_gemm()
{
    __shared__ alignas(16) char smem[4 * STAGE_B];
    const uint32_t sb = smem_u32(smem);

    const int kb = blockIdx.x;          // 0..1  (fastest: peers share V in L2)
    const int tb = blockIdx.y;          // 0..240
    const int p  = blockIdx.z;          // 0..15

    const int tid  = threadIdx.x;
    const int wid  = tid >> 5, lane = tid & 31;
    const int g    = lane >> 2, tig = lane & 3;
    const int wk   = (wid & 3) * 32;
    const int wt   = (wid >> 2) * 64;

    // ---- cp.async loader role: all 256 threads, 2 x 16B each per chunk ----
    const __half* gptr;
    size_t gstep;
    uint32_t soff;
    {
        if (tid < 128) {                 // U: 16 c-rows x 128 k halves
            int row = tid >> 3, seg = tid & 7;
            gptr  = g_U16 + ((size_t)p * Cc + row) * Kk + kb * 128 + seg * 8;
            gstep = (size_t)16 * Kk;
            soff  = (uint32_t)(row * PITCH_B + seg * 16);
        } else {                         // V: 16 c-rows x 128 t halves
            int j = tid - 128;
            int row = j >> 3, seg = j & 7;
            gptr  = g_V16 + ((size_t)p * Cc + row) * NTP + (size_t)tb * 128 + seg * 8;
            gstep = (size_t)16 * NTP;
            soff  = (uint32_t)(UREG_B + row * PITCH_B + seg * 16);
        }
    }

    // ---- ldmatrix lane offsets -----------------------------------------
    const uint32_t aoff0 = (uint32_t)(((lane & 7) + ((lane >> 4) & 1) * 8) * PITCH_B
                                      + (wk + ((lane >> 3) & 1) * 8) * 2);
    const uint32_t boff0 = (uint32_t)(UREG_B
                                      + ((lane & 7) + ((lane >> 3) & 1) * 8) * PITCH_B
                                      + (wt + ((lane >> 4) & 1) * 8) * 2);

    float acc[2][8][4];
    #pragma unroll
    for (int mi = 0; mi < 2; mi++)
        #pragma unroll
        for (int nj = 0; nj < 8; nj++)
            #pragma unroll
            for (int q = 0; q < 4; q++)
                acc[mi][nj][q] = 0.0f;

    // ---- prefetch stages 0..2 ------------------------------------------
    #pragma unroll
    for (int s = 0; s < 3; s++) {
        uint32_t d = sb + (uint32_t)s * STAGE_B + soff;
        cp16(d,       gptr + (size_t)s * gstep);
        cp16(d + 128, gptr + (size_t)s * gstep + 64);
        asm volatile("cp.async.commit_group;" ::: "memory");
    }

    // ---- mainloop: 8 chunks of 16 c --------------------------------------
    #pragma unroll 1
    for (int it = 0; it < 8; it++) {
        asm volatile("cp.async.wait_group %0;" :: "n"(2) : "memory");
        __syncthreads();

        const uint32_t buf = sb + (uint32_t)(it & 3) * STAGE_B;

        uint32_t a[2][4];
        ldmx4(a[0], buf + aoff0);
        ldmx4(a[1], buf + aoff0 + 32);          // mi=1: m0+16 halves
        uint32_t bb[4][4];
        #pragma unroll
        for (int njp = 0; njp < 4; njp++)
            ldmx4(bb[njp], buf + boff0 + njp * 32);

        #pragma unroll
        for (int mi = 0; mi < 2; mi++)
            #pragma unroll
            for (int njp = 0; njp < 4; njp++) {
                mma_f16(acc[mi][njp * 2 + 0], a[mi], &bb[njp][0]);
                mma_f16(acc[mi][njp * 2 + 1], a[mi], &bb[njp][2]);
            }

        int nx = it + 3;
        if (nx < 8) {
            uint32_t d = sb + (uint32_t)(nx & 3) * STAGE_B + soff;
            cp16(d,       gptr + (size_t)nx * gstep);
            cp16(d + 128, gptr + (size_t)nx * gstep + 64);
        }
        asm volatile("cp.async.commit_group;" ::: "memory");
    }

    // ---- epilogue: fp16 M stores (half2 pairs along t) -------------------
    __half* Mp = g_M16 + ((size_t)p * Kk + kb * 128 + wk) * NTP + (size_t)tb * 128 + wt;
    #pragma unroll
    for (int mi = 0; mi < 2; mi++) {
        #pragma unroll
        for (int nj = 0; nj < 8; nj++) {
            int t_off = nj * 8 + 2 * tig;
            __half* r0 = Mp + (size_t)(mi * 16 + g) * NTP + t_off;
            *(__half2*)r0                     = __floats2half2_rn(acc[mi][nj][0], acc[mi][nj][1]);
            *(__half2*)(r0 + (size_t)8 * NTP) = __floats2half2_rn(acc[mi][nj][2], acc[mi][nj][3]);
        }
    }
}

// ---------------------------------------------------------------------------
// 4) Inverse transform + bias (fp16 M reads, DRAM roofline)
// ---------------------------------------------------------------------------
__global__ void out_xform(const float* __restrict__ bias, float* __restrict__ out)
{
    unsigned idx = blockIdx.x * blockDim.x + threadIdx.x;   // < Kk*NT exact
    unsigned k = idx / NT;
    unsigned t = idx - k * NT;
    unsigned b  = t / 961u;
    unsigned r  = t - b * 961u;
    unsigned pp = r / 31u;
    unsigned qq = r - pp * 31u;

    float m[16];
    #pragma unroll
    for (int p = 0; p < 16; p++)
        m[p] = __half2float(g_M16[((size_t)p * Kk + k) * NTP + t]);

    float s0[4], s1[4];
    #pragma unroll
    for (int j = 0; j < 4; j++) {
        s0[j] = m[j] + m[4 + j] + m[8 + j];
        s1[j] = m[4 + j] - m[8 + j] - m[12 + j];
    }
    float bv = __ldg(bias + k);
    float y00 = s0[0] + s0[1] + s0[2] + bv;
    float y01 = s0[1] - s0[2] - s0[3] + bv;
    float y10 = s1[0] + s1[1] + s1[2] + bv;
    float y11 = s1[1] - s1[2] - s1[3] + bv;

    float* op = out + (((size_t)b * Kk + k) * OH + 2u * pp) * OW + 2u * qq;
    *(float2*)op        = make_float2(y00, y01);
    *(float2*)(op + OW) = make_float2(y10, y11);
}

// ---------------------------------------------------------------------------
extern "C" void kernel_launch(void* const* d_in, const int* in_sizes, int n_in,
                              void* d_out, int out_size)
{
    const float* x    = (const float*)d_in[0];
    const float* w    = (const float*)d_in[1];
    const float* bias = (const float*)d_in[2];
    float* out        = (float*)d_out;

    filt_xform<<<(Kk * Cc) / 256, 256>>>(w);
    in_xform<<<(Cc * NT) / 256, 256>>>(x);
    dim3 g3(2, 241, 16);                       // (kb, tb, p), kb fastest
    wino_gemm<<<g3, 256>>>();
    out_xform<<<(Kk * NT) / 256, 256>>>(bias, out);
}

// round 11
// speedup vs baseline: 2.2693x; 1.0873x over previous
#include <cuda_runtime.h>
#include <cuda_fp16.h>
#include <stdint.h>

// ---------------------------------------------------------------------------
// Winograd F(2,3) valid conv, fp16 mma.sync (m16n8k16, fp32 accum):
//   1) filt_xform : U[p][c][k] = G g G^T   (fp16, k-contig)
//   2) in_xform   : V[p][c][t] = B^T d B   (fp16, t-contig, 2 tiles/thread)
//   3) wino_gemm  : M[p][k][t] = sum_c U*V (fp16 HMMA, fp32 acc, fp16 M)
//   4) out_xform  : Y = A^T M A + bias     (2 tiles/thread, half2 loads)
// Round-11: tile rows padded to 32 (t = (b*31+pp)*32 + qq, NTP=31744).
// Pad t-columns are never read (M[k][t] depends only on V[.][t]), so no
// zero-fill is needed.  Both transforms vectorized; GEMM unchanged.
// ---------------------------------------------------------------------------

#define Bn 32
#define Cc 128
#define Hh 64
#define Ww 64
#define Kk 256
#define NBR 992               /* tile rows: 32 b * 31 pp */
#define NTP 31744             /* 992 * 32 = 248 * 128 */
#define OH 62
#define OW 62

__device__ __half g_U16[16 * Cc * Kk];    //   1 MB  [p][c][k]
__device__ __half g_V16[16 * Cc * NTP];   // 130 MB  [p][c][t]
__device__ __half g_M16[16 * Kk * NTP];   // 260 MB  [p][k][t]

__device__ __forceinline__ uint32_t smem_u32(const void* p) {
    uint32_t a;
    asm("{ .reg .u64 t; cvta.to.shared.u64 t, %1; cvt.u32.u64 %0, t; }" : "=r"(a) : "l"(p));
    return a;
}
__device__ __forceinline__ void cp16(uint32_t dst, const void* src) {
    asm volatile("cp.async.cg.shared.global [%0], [%1], 16;" :: "r"(dst), "l"(src));
}
__device__ __forceinline__ void ldmx4(uint32_t* r, uint32_t addr) {
    asm volatile("ldmatrix.sync.aligned.m8n8.x4.trans.shared.b16 {%0,%1,%2,%3}, [%4];"
                 : "=r"(r[0]), "=r"(r[1]), "=r"(r[2]), "=r"(r[3]) : "r"(addr));
}
__device__ __forceinline__ void mma_f16(float* d, const uint32_t* a, const uint32_t* b) {
    asm volatile(
        "mma.sync.aligned.m16n8k16.row.col.f32.f16.f16.f32 "
        "{%0,%1,%2,%3}, {%4,%5,%6,%7}, {%8,%9}, {%0,%1,%2,%3};"
        : "+f"(d[0]), "+f"(d[1]), "+f"(d[2]), "+f"(d[3])
        : "r"(a[0]), "r"(a[1]), "r"(a[2]), "r"(a[3]), "r"(b[0]), "r"(b[1]));
}

// ---------------------------------------------------------------------------
// 1) Filter transform -> U[p][c][k] fp16
// ---------------------------------------------------------------------------
__global__ void filt_xform(const float* __restrict__ w)
{
    int idx = blockIdx.x * blockDim.x + threadIdx.x;   // 32768
    int k = idx >> 7;
    int c = idx & 127;
    const float* g = w + (size_t)(k * Cc + c) * 9;

    float w00 = g[0], w01 = g[1], w02 = g[2];
    float w10 = g[3], w11 = g[4], w12 = g[5];
    float w20 = g[6], w21 = g[7], w22 = g[8];

    float t[4][3];
    t[0][0] = w00;                      t[0][1] = w01;                      t[0][2] = w02;
    t[1][0] = 0.5f * (w00 + w10 + w20); t[1][1] = 0.5f * (w01 + w11 + w21); t[1][2] = 0.5f * (w02 + w12 + w22);
    t[2][0] = 0.5f * (w00 - w10 + w20); t[2][1] = 0.5f * (w01 - w11 + w21); t[2][2] = 0.5f * (w02 - w12 + w22);
    t[3][0] = w20;                      t[3][1] = w21;                      t[3][2] = w22;

    #pragma unroll
    for (int a = 0; a < 4; a++) {
        float u0 = t[a][0];
        float u1 = 0.5f * (t[a][0] + t[a][1] + t[a][2]);
        float u2 = 0.5f * (t[a][0] - t[a][1] + t[a][2]);
        float u3 = t[a][2];
        g_U16[((size_t)(a * 4 + 0) * Cc + c) * Kk + k] = __float2half_rn(u0);
        g_U16[((size_t)(a * 4 + 1) * Cc + c) * Kk + k] = __float2half_rn(u1);
        g_U16[((size_t)(a * 4 + 2) * Cc + c) * Kk + k] = __float2half_rn(u2);
        g_U16[((size_t)(a * 4 + 3) * Cc + c) * Kk + k] = __float2half_rn(u3);
    }
}

// ---------------------------------------------------------------------------
// 2) Input transform -> V[p][c][t], 2 horizontal tiles per thread.
//    Thread (c, brow, j): tiles qq = 2j, 2j+1 (j==15: only qq=30).
//    Row transform (B^T d) over 6 shared columns computed once.
//    idx range = 128 * 992 * 16 = 2,031,616 = 7936 blocks * 256.
// ---------------------------------------------------------------------------
__global__ void in_xform(const float* __restrict__ x)
{
    unsigned idx = blockIdx.x * blockDim.x + threadIdx.x;
    unsigned j    = idx & 15u;
    unsigned rest = idx >> 4;           // c * 992 + brow
    unsigned c    = rest / NBR;
    unsigned brow = rest - c * NBR;
    unsigned b    = brow / 31u;
    unsigned pp   = brow - b * 31u;
    int qq0 = 2 * j;

    const float* xp = x + (((size_t)(b * Cc + c) * Hh + 2u * pp) * Ww + 2 * qq0);

    float d[4][6];
    if (j < 15) {
        #pragma unroll
        for (int i = 0; i < 4; i++) {
            float2 l0 = *(const float2*)(xp + i * Ww);
            float2 l1 = *(const float2*)(xp + i * Ww + 2);
            float2 l2 = *(const float2*)(xp + i * Ww + 4);
            d[i][0] = l0.x; d[i][1] = l0.y; d[i][2] = l1.x;
            d[i][3] = l1.y; d[i][4] = l2.x; d[i][5] = l2.y;
        }
    } else {
        #pragma unroll
        for (int i = 0; i < 4; i++) {
            float2 l0 = *(const float2*)(xp + i * Ww);
            float2 l1 = *(const float2*)(xp + i * Ww + 2);
            d[i][0] = l0.x; d[i][1] = l0.y; d[i][2] = l1.x;
            d[i][3] = l1.y; d[i][4] = 0.f;  d[i][5] = 0.f;
        }
    }

    // row transform over the 6 shared columns
    float tm[4][6];
    #pragma unroll
    for (int jj = 0; jj < 6; jj++) {
        tm[0][jj] = d[0][jj] - d[2][jj];
        tm[1][jj] = d[1][jj] + d[2][jj];
        tm[2][jj] = d[2][jj] - d[1][jj];
        tm[3][jj] = d[1][jj] - d[3][jj];
    }

    size_t t0 = (size_t)brow * 32 + qq0;
    #pragma unroll
    for (int a = 0; a < 4; a++) {
        float vA0 = tm[a][0] - tm[a][2];
        float vA1 = tm[a][1] + tm[a][2];
        float vA2 = tm[a][2] - tm[a][1];
        float vA3 = tm[a][1] - tm[a][3];
        float vB0 = tm[a][2] - tm[a][4];
        float vB1 = tm[a][3] + tm[a][4];
        float vB2 = tm[a][4] - tm[a][3];
        float vB3 = tm[a][3] - tm[a][5];
        *(__half2*)&g_V16[((size_t)(a * 4 + 0) * Cc + c) * NTP + t0] = __floats2half2_rn(vA0, vB0);
        *(__half2*)&g_V16[((size_t)(a * 4 + 1) * Cc + c) * NTP + t0] = __floats2half2_rn(vA1, vB1);
        *(__half2*)&g_V16[((size_t)(a * 4 + 2) * Cc + c) * NTP + t0] = __floats2half2_rn(vA2, vB2);
        *(__half2*)&g_V16[((size_t)(a * 4 + 3) * Cc + c) * NTP + t0] = __floats2half2_rn(vA3, vB3);
    }
}

// ---------------------------------------------------------------------------
// 3) fp16 tensor GEMM (unchanged except NTP):  M[k][t] = sum_c U[c][k]*V[c][t]
//    CTA 128k x 128t, 256 thr, warp 32k x 64t, 16-c chunks, cp.async ring.
//    grid = (kb=2 fastest, tb=248, p=16)
// ---------------------------------------------------------------------------
#define PITCH_B 272             /* bytes per smem row (136 halves) */
#define UREG_B  4352            /* 16 rows * 272 */
#define STAGE_B 8704            /* U + V regions */

__global__ void __launch_bounds__(256, 2) wino_gemm()
{
    __shared__ alignas(16) char smem[4 * STAGE_B];
    const uint32_t sb = smem_u32(smem);

    const int kb = blockIdx.x;          // 0..1
    const int tb = blockIdx.y;          // 0..247
    const int p  = blockIdx.z;          // 0..15

    const int tid  = threadIdx.x;
    const int wid  = tid >> 5, lane = tid & 31;
    const int g    = lane >> 2, tig = lane & 3;
    const int wk   = (wid & 3) * 32;
    const int wt   = (wid >> 2) * 64;

    const __half* gptr;
    size_t gstep;
    uint32_t soff;
    {
        if (tid < 128) {                 // U: 16 c-rows x 128 k halves
            int row = tid >> 3, seg = tid & 7;
            gptr  = g_U16 + ((size_t)p * Cc + row) * Kk + kb * 128 + seg * 8;
            gstep = (size_t)16 * Kk;
            soff  = (uint32_t)(row * PITCH_B + seg * 16);
        } else {                         // V: 16 c-rows x 128 t halves
            int jj = tid - 128;
            int row = jj >> 3, seg = jj & 7;
            gptr  = g_V16 + ((size_t)p * Cc + row) * NTP + (size_t)tb * 128 + seg * 8;
            gstep = (size_t)16 * NTP;
            soff  = (uint32_t)(UREG_B + row * PITCH_B + seg * 16);
        }
    }

    const uint32_t aoff0 = (uint32_t)(((lane & 7) + ((lane >> 4) & 1) * 8) * PITCH_B
                                      + (wk + ((lane >> 3) & 1) * 8) * 2);
    const uint32_t boff0 = (uint32_t)(UREG_B
                                      + ((lane & 7) + ((lane >> 3) & 1) * 8) * PITCH_B
                                      + (wt + ((lane >> 4) & 1) * 8) * 2);

    float acc[2][8][4];
    #pragma unroll
    for (int mi = 0; mi < 2; mi++)
        #pragma unroll
        for (int nj = 0; nj < 8; nj++)
            #pragma unroll
            for (int q = 0; q < 4; q++)
                acc[mi][nj][q] = 0.0f;

    #pragma unroll
    for (int s = 0; s < 3; s++) {
        uint32_t dst = sb + (uint32_t)s * STAGE_B + soff;
        cp16(dst,       gptr + (size_t)s * gstep);
        cp16(dst + 128, gptr + (size_t)s * gstep + 64);
        asm volatile("cp.async.commit_group;" ::: "memory");
    }

    #pragma unroll 1
    for (int it = 0; it < 8; it++) {
        asm volatile("cp.async.wait_group %0;" :: "n"(2) : "memory");
        __syncthreads();

        const uint32_t buf = sb + (uint32_t)(it & 3) * STAGE_B;

        uint32_t a[2][4];
        ldmx4(a[0], buf + aoff0);
        ldmx4(a[1], buf + aoff0 + 32);
        uint32_t bb[4][4];
        #pragma unroll
        for (int njp = 0; njp < 4; njp++)
            ldmx4(bb[njp], buf + boff0 + njp * 32);

        #pragma unroll
        for (int mi = 0; mi < 2; mi++)
            #pragma unroll
            for (int njp = 0; njp < 4; njp++) {
                mma_f16(acc[mi][njp * 2 + 0], a[mi], &bb[njp][0]);
                mma_f16(acc[mi][njp * 2 + 1], a[mi], &bb[njp][2]);
            }

        int nx = it + 3;
        if (nx < 8) {
            uint32_t dst = sb + (uint32_t)(nx & 3) * STAGE_B + soff;
            cp16(dst,       gptr + (size_t)nx * gstep);
            cp16(dst + 128, gptr + (size_t)nx * gstep + 64);
        }
        asm volatile("cp.async.commit_group;" ::: "memory");
    }

    __half* Mp = g_M16 + ((size_t)p * Kk + kb * 128 + wk) * NTP + (size_t)tb * 128 + wt;
    #pragma unroll
    for (int mi = 0; mi < 2; mi++) {
        #pragma unroll
        for (int nj = 0; nj < 8; nj++) {
            int t_off = nj * 8 + 2 * tig;
            __half* r0 = Mp + (size_t)(mi * 16 + g) * NTP + t_off;
            *(__half2*)r0                     = __floats2half2_rn(acc[mi][nj][0], acc[mi][nj][1]);
            *(__half2*)(r0 + (size_t)8 * NTP) = __floats2half2_rn(acc[mi][nj][2], acc[mi][nj][3]);
        }
    }
}

// ---------------------------------------------------------------------------
// 4) Inverse transform + bias, 2 tiles per thread (half2 M loads).
//    idx range = Kk * 15872 = 4,063,232 = 15872 blocks * 256.
// ---------------------------------------------------------------------------
__global__ void out_xform(const float* __restrict__ bias, float* __restrict__ out)
{
    unsigned idx = blockIdx.x * blockDim.x + threadIdx.x;
    unsigned k  = idx / (NTP / 2u);
    unsigned tp = idx - k * (NTP / 2u);
    unsigned t  = 2u * tp;
    unsigned qq   = t & 31u;
    unsigned brow = t >> 5;
    unsigned b    = brow / 31u;
    unsigned pp   = brow - b * 31u;

    float mA[16], mB[16];
    #pragma unroll
    for (int p = 0; p < 16; p++) {
        __half2 h = *(const __half2*)&g_M16[((size_t)p * Kk + k) * NTP + t];
        float2 f = __half22float2(h);
        mA[p] = f.x; mB[p] = f.y;
    }

    float bv = __ldg(bias + k);

    float sA0[4], sA1[4], sB0[4], sB1[4];
    #pragma unroll
    for (int jj = 0; jj < 4; jj++) {
        sA0[jj] = mA[jj] + mA[4 + jj] + mA[8 + jj];
        sA1[jj] = mA[4 + jj] - mA[8 + jj] - mA[12 + jj];
        sB0[jj] = mB[jj] + mB[4 + jj] + mB[8 + jj];
        sB1[jj] = mB[4 + jj] - mB[8 + jj] - mB[12 + jj];
    }
    float yA00 = sA0[0] + sA0[1] + sA0[2] + bv;
    float yA01 = sA0[1] - sA0[2] - sA0[3] + bv;
    float yA10 = sA1[0] + sA1[1] + sA1[2] + bv;
    float yA11 = sA1[1] - sA1[2] - sA1[3] + bv;
    float yB00 = sB0[0] + sB0[1] + sB0[2] + bv;
    float yB01 = sB0[1] - sB0[2] - sB0[3] + bv;
    float yB10 = sB1[0] + sB1[1] + sB1[2] + bv;
    float yB11 = sB1[1] - sB1[2] - sB1[3] + bv;

    float* op = out + (((size_t)b * Kk + k) * OH + 2u * pp) * OW + 2u * qq;
    if (qq < 30u) {
        *(float4*)op = make_float4(yA00, yA01, yB00, yB01);   // 16B aligned
        *(float2*)(op + OW)     = make_float2(yA10, yA11);    // op+OW only 8B aligned
        *(float2*)(op + OW + 2) = make_float2(yB10, yB11);
    } else {                       // qq == 30: second tile is pad
        *(float2*)op        = make_float2(yA00, yA01);
        *(float2*)(op + OW) = make_float2(yA10, yA11);
    }
}

// ---------------------------------------------------------------------------
extern "C" void kernel_launch(void* const* d_in, const int* in_sizes, int n_in,
                              void* d_out, int out_size)
{
    const float* x    = (const float*)d_in[0];
    const float* w    = (const float*)d_in[1];
    const float* bias = (const float*)d_in[2];
    float* out        = (float*)d_out;

    filt_xform<<<(Kk * Cc) / 256, 256>>>(w);
    in_xform<<<(Cc * NBR * 16) / 256, 256>>>(x);          // 7936 blocks
    dim3 g3(2, NTP / 128, 16);                            // (kb, tb, p)
    wino_gemm<<<g3, 256>>>();
    out_xform<<<(Kk * (NTP / 2)) / 256, 256>>>(bias, out); // 15872 blocks
}